// round 8
// baseline (speedup 1.0000x reference)
#include <cuda_runtime.h>
#include <math.h>
#include <stdint.h>

#define NE   8
#define HD   2048
#define ID   1024
#define TMAX 8192
#define RMAX (2*TMAX)

#define KC     64                   // K int8 elems per chunk (64 bytes/row)
#define NST    3
#define ROWB   64
#define A_ROWS 128
#define B_ROWS 64
#define A_T    (A_ROWS*ROWB)        // 8192 per limb
#define B_T    (B_ROWS*ROWB)        // 4096 per limb
#define STG_B  (2*A_T + 2*B_T)      // 24576
#define DSMEM  (NST*STG_B)          // 73728 -> 2 CTAs/SM

// ---------------- persistent device scratch ----------------
__device__ int   g_cnt[NE];
__device__ int   g_off[NE + 1];
__device__ int   g_list[NE][TMAX];
__device__ float g_wt[NE][TMAX];
__device__ int4  g_slot[TMAX];
__device__ __align__(256) int8_t g_xq1[(size_t)TMAX * HD];
__device__ __align__(256) int8_t g_xq2[(size_t)TMAX * HD];
__device__ float g_xs[TMAX];
__device__ __align__(256) int8_t g_fcq1[(size_t)NE * 2 * ID * HD];
__device__ __align__(256) int8_t g_fcq2[(size_t)NE * 2 * ID * HD];
__device__ float g_fcs[NE * 2 * ID];
__device__ __align__(256) int8_t g_wpq1[(size_t)NE * HD * ID];
__device__ __align__(256) int8_t g_wpq2[(size_t)NE * HD * ID];
__device__ float g_wps[NE * HD];
__device__ __align__(256) int8_t g_hq1[(size_t)RMAX * ID];
__device__ __align__(256) int8_t g_hq2[(size_t)RMAX * ID];
__device__ float g_hs[RMAX];
__device__ __align__(256) float g_fc[(size_t)RMAX * 2048];   // FC out, then proj out

// ---------------- PTX helpers ----------------
__device__ __forceinline__ uint32_t smem_u32(const void* p) {
    uint32_t a;
    asm("{ .reg .u64 t; cvta.to.shared.u64 t, %1; cvt.u32.u64 %0, t; }" : "=r"(a) : "l"(p));
    return a;
}
__device__ __forceinline__ void cp16(uint32_t d, const void* s) {
    asm volatile("cp.async.cg.shared.global [%0], [%1], 16;\n" :: "r"(d), "l"(s));
}
#define CP_COMMIT() asm volatile("cp.async.commit_group;\n" ::: "memory")
#define CP_WAIT1()  asm volatile("cp.async.wait_group 1;\n" ::: "memory")

__device__ __forceinline__ void ldsm4(uint32_t r[4], uint32_t addr) {
    asm volatile("ldmatrix.sync.aligned.m8n8.x4.shared.b16 {%0,%1,%2,%3}, [%4];\n"
                 : "=r"(r[0]), "=r"(r[1]), "=r"(r[2]), "=r"(r[3]) : "r"(addr));
}
__device__ __forceinline__ void imma(int c[4], const uint32_t a[4], const uint32_t b[2]) {
    asm volatile(
        "mma.sync.aligned.m16n8k32.row.col.s32.s8.s8.s32 "
        "{%0,%1,%2,%3}, {%4,%5,%6,%7}, {%8,%9}, {%0,%1,%2,%3};\n"
        : "+r"(c[0]), "+r"(c[1]), "+r"(c[2]), "+r"(c[3])
        : "r"(a[0]), "r"(a[1]), "r"(a[2]), "r"(a[3]), "r"(b[0]), "r"(b[1]));
}
__device__ __forceinline__ uint32_t pack4(int a, int b, int c, int d) {
    return (uint32_t)(a & 0xff) | ((uint32_t)(b & 0xff) << 8) |
           ((uint32_t)(c & 0xff) << 16) | ((uint32_t)d << 24);
}

// ---------------- quantize: fp32 row -> int8 q1,q2 + scale (device-side ptrs!) ----------------
template<int L>
__device__ __forceinline__ void quant_row(const float* __restrict__ src,
                                          int8_t* __restrict__ q1o,
                                          int8_t* __restrict__ q2o,
                                          float* __restrict__ so) {
    constexpr int E = L / 256;
    int r = blockIdx.x, tid = threadIdx.x;
    const float* row = src + (size_t)r * L;
    float v[E];
    float m = 0.f;
#pragma unroll
    for (int j = 0; j < E; j += 4) {
        float4 f = *(const float4*)(row + tid * E + j);
        v[j] = f.x; v[j+1] = f.y; v[j+2] = f.z; v[j+3] = f.w;
        m = fmaxf(m, fmaxf(fmaxf(fabsf(f.x), fabsf(f.y)), fmaxf(fabsf(f.z), fabsf(f.w))));
    }
    __shared__ float red[8];
#pragma unroll
    for (int o = 16; o; o >>= 1) m = fmaxf(m, __shfl_xor_sync(~0u, m, o));
    if ((tid & 31) == 0) red[tid >> 5] = m;
    __syncthreads();
    if (tid < 8) {
        float t = red[tid];
#pragma unroll
        for (int o = 4; o; o >>= 1) t = fmaxf(t, __shfl_xor_sync(0xffu, t, o));
        if (tid == 0) red[0] = fmaxf(t, 1e-30f);
    }
    __syncthreads();
    float mx = red[0];
    if (tid == 0) so[r] = mx * (1.f / 127.f);
    float inv = 127.f / mx;
#pragma unroll
    for (int j = 0; j < E; j += 4) {
        int qa[4], qb[4];
#pragma unroll
        for (int k = 0; k < 4; k++) {
            float f = v[j + k] * inv;
            int q = __float2int_rn(f);
            qa[k] = q;
            qb[k] = __float2int_rn((f - (float)q) * 254.f);
        }
        *(uint32_t*)(q1o + (size_t)r * L + tid * E + j) = pack4(qa[0], qa[1], qa[2], qa[3]);
        *(uint32_t*)(q2o + (size_t)r * L + tid * E + j) = pack4(qb[0], qb[1], qb[2], qb[3]);
    }
}

// thin wrappers: device-global symbols resolved in DEVICE code
__global__ void quant_x_kernel(const float* __restrict__ x) {
    if (blockIdx.x == 0 && threadIdx.x < NE) g_cnt[threadIdx.x] = 0;
    quant_row<HD>(x, g_xq1, g_xq2, g_xs);
}
__global__ void quant_wfc_kernel(const float* __restrict__ wfc) {
    quant_row<HD>(wfc, g_fcq1, g_fcq2, g_fcs);
}
__global__ void quant_wp_kernel(const float* __restrict__ wp) {
    quant_row<ID>(wp, g_wpq1, g_wpq2, g_wps);
}

// ---------------- router ----------------
__global__ void router_kernel(const float* __restrict__ x,
                              const float* __restrict__ wg,
                              float* __restrict__ out_logits, int T) {
    int warp = (blockIdx.x * blockDim.x + threadIdx.x) >> 5;
    int lane = threadIdx.x & 31;
    if (warp >= T) return;
    const float* xr = x + (size_t)warp * HD;

    float acc[NE];
#pragma unroll
    for (int e = 0; e < NE; e++) acc[e] = 0.f;
    for (int h = lane; h < HD; h += 32) {
        float xv = xr[h];
#pragma unroll
        for (int e = 0; e < NE; e++) acc[e] = fmaf(xv, wg[e * HD + h], acc[e]);
    }
#pragma unroll
    for (int e = 0; e < NE; e++) {
#pragma unroll
        for (int o = 16; o > 0; o >>= 1)
            acc[e] += __shfl_xor_sync(0xffffffffu, acc[e], o);
    }
    if (out_logits && lane < NE)
        out_logits[(size_t)warp * NE + lane] = acc[lane];
    if (lane == 0) {
        int i0 = 0; float v0 = acc[0];
#pragma unroll
        for (int e = 1; e < NE; e++) if (acc[e] > v0) { v0 = acc[e]; i0 = e; }
        int i1 = -1; float v1 = -1e30f;
#pragma unroll
        for (int e = 0; e < NE; e++) if (e != i0 && acc[e] > v1) { v1 = acc[e]; i1 = e; }
        float e1 = expf(v1 - v0);
        float w0 = 1.f / (1.f + e1);
        float w1 = e1 * w0;
        int p0 = atomicAdd(&g_cnt[i0], 1);
        g_list[i0][p0] = warp; g_wt[i0][p0] = w0;
        int p1 = atomicAdd(&g_cnt[i1], 1);
        g_list[i1][p1] = warp; g_wt[i1][p1] = w1;
        g_slot[warp] = make_int4(i0, p0, i1, p1);
    }
}

__global__ void offsets_kernel() {
    if (threadIdx.x == 0) {
        int s = 0;
        for (int e = 0; e < NE; e++) { g_off[e] = s; s += g_cnt[e]; }
        g_off[NE] = s;
    }
}

// ================= int8 split GEMM mainloop =================
// CTA 128x64, 256 threads, 8 warps of 64x16, 3-term IMMA k32.
struct QPtrs { const char *a1, *a2, *b1, *b2; };

__device__ __forceinline__ void gemm_mainloop(
    uint32_t sb, const QPtrs& p, int tid, int NK,
    int accM[4][2][4], int accC[4][2][4])
{
    // A loader: thread t -> row t>>1, chunks {2(t&1), 2(t&1)+1}
    int arow = tid >> 1;
    int c0   = (tid & 1) * 2;
    int srA  = (arow >> 1) & 3;
    uint32_t dA0 = sb + (uint32_t)arow * ROWB + ((uint32_t)(c0 ^ srA) << 4);
    uint32_t dA1 = sb + (uint32_t)arow * ROWB + ((uint32_t)((c0 + 1) ^ srA) << 4);
    int sA0 = c0 * 16, sA1 = sA0 + 16;
    // B loader: thread t -> row t>>2, chunk t&3
    int brow = tid >> 2;
    int bc   = tid & 3;
    int srB  = (brow >> 1) & 3;
    uint32_t dB = sb + 2 * A_T + (uint32_t)brow * ROWB + ((uint32_t)(bc ^ srB) << 4);
    int sB0 = bc * 16;

    auto load_stage = [&](int s, int kc) {
        uint32_t st = (uint32_t)s * STG_B;
        int go = kc * KC;
        cp16(dA0 + st,        p.a1 + go + sA0); cp16(dA1 + st,        p.a1 + go + sA1);
        cp16(dA0 + st + A_T,  p.a2 + go + sA0); cp16(dA1 + st + A_T,  p.a2 + go + sA1);
        cp16(dB + st,         p.b1 + go + sB0);
        cp16(dB + st + B_T,   p.b2 + go + sB0);
    };

    int wid = tid >> 5, lane = tid & 31;
    int wm = (wid & 1) * 64, wn = (wid >> 1) * 16;
    uint32_t aBase = sb + (uint32_t)(wm + (lane & 15)) * ROWB;
    uint32_t sAx = ((lane & 15) >> 1) & 3;
    uint32_t hA  = (lane >> 4) & 1;
    uint32_t bBase = sb + 2 * A_T + (uint32_t)(wn + 8 * ((lane >> 4) & 1) + (lane & 7)) * ROWB;
    uint32_t sBx = ((lane & 7) >> 1) & 3;
    uint32_t hB  = (lane >> 3) & 1;

    load_stage(0, 0); CP_COMMIT();
    load_stage(1, 1); CP_COMMIT();

    for (int kc = 0; kc < NK; kc++) {
        CP_WAIT1();
        __syncthreads();
        int kn = kc + 2;
        if (kn < NK) load_stage(kn % NST, kn);
        CP_COMMIT();
        uint32_t st = (uint32_t)(kc % NST) * STG_B;
#pragma unroll
        for (int ks = 0; ks < 2; ks++) {           // two k32 steps per 64B chunk
            uint32_t ca = ((2u * ks + hA) ^ sAx) << 4;
            uint32_t cb = ((2u * ks + hB) ^ sBx) << 4;
            uint32_t b1f[4], b2f[4];
            ldsm4(b1f, bBase + st + cb);
            ldsm4(b2f, bBase + st + B_T + cb);
#pragma unroll
            for (int mt = 0; mt < 4; mt++) {
                uint32_t a1f[4], a2f[4];
                ldsm4(a1f, aBase + st + mt * (16 * ROWB) + ca);
                ldsm4(a2f, aBase + st + A_T + mt * (16 * ROWB) + ca);
#pragma unroll
                for (int nt = 0; nt < 2; nt++) {
                    imma(accM[mt][nt], a1f, b1f + 2 * nt);
                    imma(accC[mt][nt], a1f, b2f + 2 * nt);
                    imma(accC[mt][nt], a2f, b1f + 2 * nt);
                }
            }
        }
    }
}

// ---------------- FC GEMM (gathered A=xq) -> g_fc fp32 ----------------
__global__ void __launch_bounds__(256, 2) fc_mma_kernel() {
    extern __shared__ char sm[];
    __shared__ int   trow[A_ROWS];
    __shared__ float sasm[A_ROWS];
    int e = blockIdx.z, cnt = g_cnt[e];
    int m0 = blockIdx.y * A_ROWS;
    if (m0 >= cnt) return;
    int n0 = blockIdx.x * B_ROWS;
    int tid = threadIdx.x;
    if (tid < A_ROWS) {
        int gi = m0 + tid;
        int tok = g_list[e][gi < cnt ? gi : cnt - 1];
        trow[tid] = tok;
        sasm[tid] = g_xs[tok];
    }
    __syncthreads();
    uint32_t sb = smem_u32(sm);

    QPtrs p;
    {
        int tok = trow[tid >> 1];
        p.a1 = (const char*)(g_xq1 + (size_t)tok * HD);
        p.a2 = (const char*)(g_xq2 + (size_t)tok * HD);
        size_t br = ((size_t)e * 2 * ID + n0 + (tid >> 2)) * HD;
        p.b1 = (const char*)(g_fcq1 + br);
        p.b2 = (const char*)(g_fcq2 + br);
    }

    int accM[4][2][4], accC[4][2][4];
#pragma unroll
    for (int mt = 0; mt < 4; mt++)
#pragma unroll
        for (int nt = 0; nt < 2; nt++)
#pragma unroll
            for (int k = 0; k < 4; k++) { accM[mt][nt][k] = 0; accC[mt][nt][k] = 0; }

    gemm_mainloop(sb, p, tid, HD / KC, accM, accC);

    int wid = tid >> 5, lane = tid & 31;
    int wm = (wid & 1) * 64, wn = (wid >> 1) * 16;
    int g = lane >> 2, t = lane & 3;
    int roff = g_off[e];
    float sbv[2][2];
#pragma unroll
    for (int nt = 0; nt < 2; nt++) {
        sbv[nt][0] = g_fcs[e * 2048 + n0 + wn + nt * 8 + t * 2];
        sbv[nt][1] = g_fcs[e * 2048 + n0 + wn + nt * 8 + t * 2 + 1];
    }
#pragma unroll
    for (int mt = 0; mt < 4; mt++) {
#pragma unroll
        for (int half = 0; half < 2; half++) {
            int r = wm + mt * 16 + g + half * 8;
            int gi = m0 + r;
            if (gi < cnt) {
                float sa = sasm[r];
                float* orow = g_fc + (size_t)(roff + gi) * 2048 + n0 + wn;
#pragma unroll
                for (int nt = 0; nt < 2; nt++) {
                    float v0 = (float)accM[mt][nt][half*2]   + (float)accC[mt][nt][half*2]   * (1.f/254.f);
                    float v1 = (float)accM[mt][nt][half*2+1] + (float)accC[mt][nt][half*2+1] * (1.f/254.f);
                    float2 v = make_float2(sa * sbv[nt][0] * v0, sa * sbv[nt][1] * v1);
                    *(float2*)(orow + nt * 8 + t * 2) = v;
                }
            }
        }
    }
}

// ---------------- GLU + quantize h ----------------
__global__ void glu_quant_kernel() {
    int r = blockIdx.x, tid = threadIdx.x;     // 256 threads, 4 elems each
    const float* row = g_fc + (size_t)r * 2048;
    float4 a = *(const float4*)(row + tid * 4);
    float4 b = *(const float4*)(row + 1024 + tid * 4);
    float v[4];
    v[0] = a.x / (1.f + expf(-a.x)) * b.x;
    v[1] = a.y / (1.f + expf(-a.y)) * b.y;
    v[2] = a.z / (1.f + expf(-a.z)) * b.z;
    v[3] = a.w / (1.f + expf(-a.w)) * b.w;
    float m = fmaxf(fmaxf(fabsf(v[0]), fabsf(v[1])), fmaxf(fabsf(v[2]), fabsf(v[3])));
    __shared__ float red[8];
#pragma unroll
    for (int o = 16; o; o >>= 1) m = fmaxf(m, __shfl_xor_sync(~0u, m, o));
    if ((tid & 31) == 0) red[tid >> 5] = m;
    __syncthreads();
    if (tid < 8) {
        float t = red[tid];
#pragma unroll
        for (int o = 4; o; o >>= 1) t = fmaxf(t, __shfl_xor_sync(0xffu, t, o));
        if (tid == 0) red[0] = fmaxf(t, 1e-30f);
    }
    __syncthreads();
    float mx = red[0];
    if (tid == 0) g_hs[r] = mx * (1.f / 127.f);
    float inv = 127.f / mx;
    int qa[4], qb[4];
#pragma unroll
    for (int k = 0; k < 4; k++) {
        float f = v[k] * inv;
        int q = __float2int_rn(f);
        qa[k] = q;
        qb[k] = __float2int_rn((f - (float)q) * 254.f);
    }
    *(uint32_t*)(g_hq1 + (size_t)r * ID + tid * 4) = pack4(qa[0], qa[1], qa[2], qa[3]);
    *(uint32_t*)(g_hq2 + (size_t)r * ID + tid * 4) = pack4(qb[0], qb[1], qb[2], qb[3]);
}

// ---------------- proj GEMM -> g_fc fp32 (reused) ----------------
__global__ void __launch_bounds__(256, 2) proj_mma_kernel() {
    extern __shared__ char sm[];
    __shared__ float sasm[A_ROWS];
    int e = blockIdx.z, cnt = g_cnt[e];
    int m0 = blockIdx.y * A_ROWS;
    if (m0 >= cnt) return;
    int n0 = blockIdx.x * B_ROWS;
    int tid = threadIdx.x;
    uint32_t sb = smem_u32(sm);
    int roff = g_off[e];
    if (tid < A_ROWS) {
        int gi = m0 + tid;
        sasm[tid] = g_hs[roff + (gi < cnt ? gi : cnt - 1)];
    }
    __syncthreads();

    QPtrs p;
    {
        int gi = m0 + (tid >> 1);
        int gic = gi < cnt ? gi : cnt - 1;
        size_t ar = (size_t)(roff + gic) * ID;
        p.a1 = (const char*)(g_hq1 + ar);
        p.a2 = (const char*)(g_hq2 + ar);
        size_t br = ((size_t)e * HD + n0 + (tid >> 2)) * ID;
        p.b1 = (const char*)(g_wpq1 + br);
        p.b2 = (const char*)(g_wpq2 + br);
    }

    int accM[4][2][4], accC[4][2][4];
#pragma unroll
    for (int mt = 0; mt < 4; mt++)
#pragma unroll
        for (int nt = 0; nt < 2; nt++)
#pragma unroll
            for (int k = 0; k < 4; k++) { accM[mt][nt][k] = 0; accC[mt][nt][k] = 0; }

    gemm_mainloop(sb, p, tid, ID / KC, accM, accC);

    int wid = tid >> 5, lane = tid & 31;
    int wm = (wid & 1) * 64, wn = (wid >> 1) * 16;
    int g = lane >> 2, t = lane & 3;
    float sbv[2][2];
#pragma unroll
    for (int nt = 0; nt < 2; nt++) {
        sbv[nt][0] = g_wps[e * 2048 + n0 + wn + nt * 8 + t * 2];
        sbv[nt][1] = g_wps[e * 2048 + n0 + wn + nt * 8 + t * 2 + 1];
    }
#pragma unroll
    for (int mt = 0; mt < 4; mt++) {
#pragma unroll
        for (int half = 0; half < 2; half++) {
            int r = wm + mt * 16 + g + half * 8;
            int gi = m0 + r;
            if (gi < cnt) {
                float sa = sasm[r];
                float* orow = g_fc + (size_t)(roff + gi) * 2048 + n0 + wn;
#pragma unroll
                for (int nt = 0; nt < 2; nt++) {
                    float v0 = (float)accM[mt][nt][half*2]   + (float)accC[mt][nt][half*2]   * (1.f/254.f);
                    float v1 = (float)accM[mt][nt][half*2+1] + (float)accC[mt][nt][half*2+1] * (1.f/254.f);
                    float2 v = make_float2(sa * sbv[nt][0] * v0, sa * sbv[nt][1] * v1);
                    *(float2*)(orow + nt * 8 + t * 2) = v;
                }
            }
        }
    }
}

// ---------------- combine ----------------
__global__ void combine_kernel(float* __restrict__ out_y, int T) {
    int idx = blockIdx.x * blockDim.x + threadIdx.x;
    int t = idx >> 9;
    if (t >= T) return;
    int c = (idx & 511) * 4;
    int4 s = g_slot[t];
    int r0 = g_off[s.x] + s.y;
    int r1 = g_off[s.z] + s.w;
    float w0 = g_wt[s.x][s.y];
    float w1 = g_wt[s.z][s.w];
    float4 p0 = *(const float4*)(g_fc + (size_t)r0 * 2048 + c);
    float4 p1 = *(const float4*)(g_fc + (size_t)r1 * 2048 + c);
    float4 v;
    v.x = w0 * p0.x + w1 * p1.x;
    v.y = w0 * p0.y + w1 * p1.y;
    v.z = w0 * p0.z + w1 * p1.z;
    v.w = w0 * p0.w + w1 * p1.w;
    *(float4*)(out_y + (size_t)t * HD + c) = v;
}

// ---------------- launch ----------------
extern "C" void kernel_launch(void* const* d_in, const int* in_sizes, int n_in,
                              void* d_out, int out_size) {
    const float* x   = (const float*)d_in[0];
    const float* wg  = (const float*)d_in[1];
    const float* wfc = (const float*)d_in[2];
    const float* wp  = (const float*)d_in[3];
    float* out = (float*)d_out;

    int T = in_sizes[0] / HD;
    if (T > TMAX) T = TMAX;

    float* out_y = out;
    long long need = (long long)T * HD + (long long)T * NE;
    float* out_logits = ((long long)out_size >= need) ? out + (size_t)T * HD : nullptr;

    cudaFuncSetAttribute(fc_mma_kernel,   cudaFuncAttributeMaxDynamicSharedMemorySize, DSMEM);
    cudaFuncSetAttribute(proj_mma_kernel, cudaFuncAttributeMaxDynamicSharedMemorySize, DSMEM);

    quant_x_kernel<<<T, 256>>>(x);
    quant_wfc_kernel<<<NE * 2 * ID, 256>>>(wfc);
    quant_wp_kernel<<<NE * HD, 256>>>(wp);
    router_kernel<<<(T * 32 + 255) / 256, 256>>>(x, wg, out_logits, T);
    offsets_kernel<<<1, 32>>>();

    dim3 g1(2 * ID / B_ROWS, TMAX / A_ROWS, NE);   // (32, 64, 8)
    fc_mma_kernel<<<g1, 256, DSMEM>>>();

    glu_quant_kernel<<<RMAX, 256>>>();

    dim3 g2(HD / B_ROWS, TMAX / A_ROWS, NE);       // (32, 64, 8)
    proj_mma_kernel<<<g2, 256, DSMEM>>>();

    int ncmb = T * (HD / 4);
    combine_kernel<<<(ncmb + 255) / 256, 256>>>(out_y, T);
}

// round 9
// speedup vs baseline: 2.9081x; 2.9081x over previous
#include <cuda_runtime.h>
#include <math.h>
#include <stdint.h>

#define NE   8
#define HD   2048
#define ID   1024
#define TMAX 8192
#define RMAX (2*TMAX)

#define KC     32                   // K fp32 elems per chunk (128 bytes/row)
#define NST    3
#define ROWB   128
#define A_ROWS 128
#define B_ROWS 128
#define A_T    (A_ROWS*ROWB)        // 16384
#define STG_B  (2*A_T)              // 32768 (A + B)
#define DSMEM  (NST*STG_B)          // 98304 -> 2 CTAs/SM

// ---------------- persistent device scratch ----------------
__device__ int   g_cnt[NE];
__device__ int   g_off[NE + 1];
__device__ int   g_list[NE][TMAX];
__device__ float g_wt[NE][TMAX];
__device__ int4  g_slot[TMAX];
__device__ __align__(256) float g_xr[(size_t)TMAX * HD];          // tf32-rounded x
__device__ __align__(256) float g_fcr[(size_t)NE * 2 * ID * HD];  // tf32-rounded w_fc
__device__ __align__(256) float g_wpr[(size_t)NE * HD * ID];      // tf32-rounded w_proj
__device__ __align__(256) float g_hr[(size_t)RMAX * ID];          // tf32-rounded GLU out
__device__ __align__(256) float g_fc[(size_t)RMAX * 2048];        // FC out, then proj out

// ---------------- PTX helpers ----------------
__device__ __forceinline__ uint32_t smem_u32(const void* p) {
    uint32_t a;
    asm("{ .reg .u64 t; cvta.to.shared.u64 t, %1; cvt.u32.u64 %0, t; }" : "=r"(a) : "l"(p));
    return a;
}
__device__ __forceinline__ void cp16(uint32_t d, const void* s) {
    asm volatile("cp.async.cg.shared.global [%0], [%1], 16;\n" :: "r"(d), "l"(s));
}
#define CP_COMMIT() asm volatile("cp.async.commit_group;\n" ::: "memory")
#define CP_WAIT1()  asm volatile("cp.async.wait_group 1;\n" ::: "memory")

__device__ __forceinline__ void ldsm4(uint32_t r[4], uint32_t addr) {
    asm volatile("ldmatrix.sync.aligned.m8n8.x4.shared.b16 {%0,%1,%2,%3}, [%4];\n"
                 : "=r"(r[0]), "=r"(r[1]), "=r"(r[2]), "=r"(r[3]) : "r"(addr));
}
__device__ __forceinline__ void mma_tf32(float c[4], const uint32_t a[4], const uint32_t b[2]) {
    asm volatile(
        "mma.sync.aligned.m16n8k8.row.col.f32.tf32.tf32.f32 "
        "{%0,%1,%2,%3}, {%4,%5,%6,%7}, {%8,%9}, {%0,%1,%2,%3};\n"
        : "+f"(c[0]), "+f"(c[1]), "+f"(c[2]), "+f"(c[3])
        : "r"(a[0]), "r"(a[1]), "r"(a[2]), "r"(a[3]), "r"(b[0]), "r"(b[1]));
}
__device__ __forceinline__ float tf32r(float f) {
    uint32_t u;
    asm("cvt.rna.tf32.f32 %0, %1;" : "=r"(u) : "f"(f));
    return __uint_as_float(u);
}

// ---------------- kernel 0: round inputs to tf32 + zero counters ----------------
#define X4   ((size_t)TMAX * HD / 4)
#define WFC4 ((size_t)NE * 2 * ID * HD / 4)
#define WP4  ((size_t)NE * HD * ID / 4)

__device__ __forceinline__ void round4(const float* src, float* dst, size_t i) {
    float4 f = *(const float4*)(src + i * 4);
    float4 o;
    o.x = tf32r(f.x); o.y = tf32r(f.y); o.z = tf32r(f.z); o.w = tf32r(f.w);
    *(float4*)(dst + i * 4) = o;
}
__global__ void prep_kernel(const float* __restrict__ x,
                            const float* __restrict__ wfc,
                            const float* __restrict__ wp) {
    if (blockIdx.x == 0 && threadIdx.x < NE) g_cnt[threadIdx.x] = 0;
    size_t i = (size_t)blockIdx.x * blockDim.x + threadIdx.x;
    if (i < X4) round4(x, g_xr, i);
    else if (i < X4 + WFC4) round4(wfc, g_fcr, i - X4);
    else if (i < X4 + WFC4 + WP4) round4(wp, g_wpr, i - X4 - WFC4);
}

// ---------------- kernel 1: router (float4 loads) ----------------
__global__ void router_kernel(const float* __restrict__ x,
                              const float* __restrict__ wg,
                              float* __restrict__ out_logits, int T) {
    int warp = (blockIdx.x * blockDim.x + threadIdx.x) >> 5;
    int lane = threadIdx.x & 31;
    if (warp >= T) return;
    const float4* xr = (const float4*)(x + (size_t)warp * HD);

    float acc[NE];
#pragma unroll
    for (int e = 0; e < NE; e++) acc[e] = 0.f;
    for (int h = lane; h < HD / 4; h += 32) {
        float4 xv = xr[h];
#pragma unroll
        for (int e = 0; e < NE; e++) {
            float4 wv = ((const float4*)(wg + e * HD))[h];
            acc[e] = fmaf(xv.x, wv.x, fmaf(xv.y, wv.y, fmaf(xv.z, wv.z, fmaf(xv.w, wv.w, acc[e]))));
        }
    }
#pragma unroll
    for (int e = 0; e < NE; e++) {
#pragma unroll
        for (int o = 16; o > 0; o >>= 1)
            acc[e] += __shfl_xor_sync(0xffffffffu, acc[e], o);
    }
    if (out_logits && lane < NE)
        out_logits[(size_t)warp * NE + lane] = acc[lane];
    if (lane == 0) {
        int i0 = 0; float v0 = acc[0];
#pragma unroll
        for (int e = 1; e < NE; e++) if (acc[e] > v0) { v0 = acc[e]; i0 = e; }
        int i1 = -1; float v1 = -1e30f;
#pragma unroll
        for (int e = 0; e < NE; e++) if (e != i0 && acc[e] > v1) { v1 = acc[e]; i1 = e; }
        float e1 = expf(v1 - v0);
        float w0 = 1.f / (1.f + e1);
        float w1 = e1 * w0;
        int p0 = atomicAdd(&g_cnt[i0], 1);
        g_list[i0][p0] = warp; g_wt[i0][p0] = w0;
        int p1 = atomicAdd(&g_cnt[i1], 1);
        g_list[i1][p1] = warp; g_wt[i1][p1] = w1;
        g_slot[warp] = make_int4(i0, p0, i1, p1);
    }
}

__global__ void offsets_kernel() {
    if (threadIdx.x == 0) {
        int s = 0;
        for (int e = 0; e < NE; e++) { g_off[e] = s; s += g_cnt[e]; }
        g_off[NE] = s;
    }
}

// ================= TF32 GEMM mainloop =================
// CTA 128x128, 256 threads, 8 warps of 64x32, single-term tf32 m16n8k8.
// 128B smem rows, 16B-chunk XOR swizzle (chunk ^= row&7), 3-stage cp.async, 2 CTAs/SM.
struct GemmPtrs { const char *gA, *gB; };   // per-thread row base pointers

__device__ __forceinline__ void gemm_mainloop(
    uint32_t sb, const GemmPtrs& p, int tid, int NK, float acc[4][4][4])
{
    // loader: thread t -> row t>>1, 64B-half t&1 (4 chunks of 16B each)
    int lrow = tid >> 1, lh = tid & 1;
    int sr = lrow & 7;
    uint32_t dA = sb + (uint32_t)lrow * ROWB;
    uint32_t dB = sb + A_T + (uint32_t)lrow * ROWB;
    int c0 = lh * 4;
    uint32_t oA[4], oB[4];
#pragma unroll
    for (int j = 0; j < 4; j++) {
        oA[j] = (uint32_t)((c0 + j) ^ sr) << 4;
        oB[j] = oA[j];
    }
    int gsrc = lh * 64;

    auto load_stage = [&](int s, int kc) {
        uint32_t st = (uint32_t)s * STG_B;
        int go = kc * 128 + gsrc;
#pragma unroll
        for (int j = 0; j < 4; j++) cp16(dA + st + oA[j], p.gA + go + j * 16);
#pragma unroll
        for (int j = 0; j < 4; j++) cp16(dB + st + oB[j], p.gB + go + j * 16);
    };

    int wid = tid >> 5, lane = tid & 31;
    int wm = (wid & 1) * 64, wn = (wid >> 1) * 32;
    // A frags: row = wm + mt*16 + (lane&15), chunk = 2ks + hA
    uint32_t aBase = sb + (uint32_t)(wm + (lane & 15)) * ROWB;
    uint32_t srA = (uint32_t)(lane & 7);
    uint32_t hA  = (lane >> 4) & 1;
    // B frags: row = wn + (lane&7) + 8*((lane>>4)&1), chunk = 2ks + hB
    uint32_t bBase = sb + A_T + (uint32_t)(wn + (lane & 7) + 8 * ((lane >> 4) & 1)) * ROWB;
    uint32_t srB = (uint32_t)(lane & 7);
    uint32_t hB  = (lane >> 3) & 1;

    load_stage(0, 0); CP_COMMIT();
    load_stage(1, 1); CP_COMMIT();

    for (int kc = 0; kc < NK; kc++) {
        CP_WAIT1();
        __syncthreads();
        int kn = kc + 2;
        if (kn < NK) load_stage(kn % NST, kn);
        CP_COMMIT();
        uint32_t st = (uint32_t)(kc % NST) * STG_B;
#pragma unroll
        for (int ks = 0; ks < 4; ks++) {           // four k8 steps per 128B chunk
            uint32_t ca = ((2u * ks + hA) ^ srA) << 4;
            uint32_t cb = ((2u * ks + hB) ^ srB) << 4;
            uint32_t bf[8];
            ldsm4(bf,     bBase + st + cb);               // n-tiles 0,1
            ldsm4(bf + 4, bBase + st + 16 * ROWB + cb);   // n-tiles 2,3
#pragma unroll
            for (int mt = 0; mt < 4; mt++) {
                uint32_t af[4];
                ldsm4(af, aBase + st + mt * (16 * ROWB) + ca);
#pragma unroll
                for (int nt = 0; nt < 4; nt++)
                    mma_tf32(acc[mt][nt], af, bf + 2 * nt);
            }
        }
    }
}

// ---------------- kernel 3: FC GEMM (gathered A=x) -> g_fc fp32 ----------------
__global__ void __launch_bounds__(256, 2) fc_mma_kernel() {
    extern __shared__ char sm[];
    __shared__ int trow[A_ROWS];
    int e = blockIdx.z, cnt = g_cnt[e];
    int m0 = blockIdx.y * A_ROWS;
    if (m0 >= cnt) return;
    int n0 = blockIdx.x * B_ROWS;
    int tid = threadIdx.x;
    if (tid < A_ROWS) { int gi = m0 + tid; trow[tid] = g_list[e][gi < cnt ? gi : cnt - 1]; }
    __syncthreads();
    uint32_t sb = smem_u32(sm);

    GemmPtrs p;
    p.gA = (const char*)(g_xr + (size_t)trow[tid >> 1] * HD);
    p.gB = (const char*)(g_fcr + ((size_t)e * 2 * ID + n0 + (tid >> 1)) * HD);

    float acc[4][4][4];
#pragma unroll
    for (int mt = 0; mt < 4; mt++)
#pragma unroll
        for (int nt = 0; nt < 4; nt++)
#pragma unroll
            for (int k = 0; k < 4; k++) acc[mt][nt][k] = 0.f;

    gemm_mainloop(sb, p, tid, HD / KC, acc);

    int wid = tid >> 5, lane = tid & 31;
    int wm = (wid & 1) * 64, wn = (wid >> 1) * 32;
    int g = lane >> 2, t = lane & 3;
    int roff = g_off[e];
#pragma unroll
    for (int mt = 0; mt < 4; mt++) {
#pragma unroll
        for (int half = 0; half < 2; half++) {
            int r = wm + mt * 16 + g + half * 8;
            int gi = m0 + r;
            if (gi < cnt) {
                float* orow = g_fc + (size_t)(roff + gi) * 2048 + n0 + wn;
#pragma unroll
                for (int nt = 0; nt < 4; nt++) {
                    float2 v = half ? make_float2(acc[mt][nt][2], acc[mt][nt][3])
                                    : make_float2(acc[mt][nt][0], acc[mt][nt][1]);
                    *(float2*)(orow + nt * 8 + t * 2) = v;
                }
            }
        }
    }
}

// ---------------- kernel 4: GLU -> g_hr (tf32-rounded fp32) ----------------
__global__ void glu_kernel() {
    int r = blockIdx.x, tid = threadIdx.x;   // 256 threads x 4 elems
    const float* row = g_fc + (size_t)r * 2048;
    float4 a = *(const float4*)(row + tid * 4);
    float4 b = *(const float4*)(row + 1024 + tid * 4);
    float4 o;
    o.x = tf32r(a.x / (1.f + expf(-a.x)) * b.x);
    o.y = tf32r(a.y / (1.f + expf(-a.y)) * b.y);
    o.z = tf32r(a.z / (1.f + expf(-a.z)) * b.z);
    o.w = tf32r(a.w / (1.f + expf(-a.w)) * b.w);
    *(float4*)(g_hr + (size_t)r * ID + tid * 4) = o;
}

// ---------------- kernel 5: proj GEMM -> g_fc fp32 (reused) ----------------
__global__ void __launch_bounds__(256, 2) proj_mma_kernel() {
    extern __shared__ char sm[];
    int e = blockIdx.z, cnt = g_cnt[e];
    int m0 = blockIdx.y * A_ROWS;
    if (m0 >= cnt) return;
    int n0 = blockIdx.x * B_ROWS;
    int tid = threadIdx.x;
    uint32_t sb = smem_u32(sm);
    int roff = g_off[e];

    GemmPtrs p;
    {
        int gi = m0 + (tid >> 1);
        int gic = gi < cnt ? gi : cnt - 1;
        p.gA = (const char*)(g_hr + (size_t)(roff + gic) * ID);
        p.gB = (const char*)(g_wpr + ((size_t)e * HD + n0 + (tid >> 1)) * ID);
    }

    float acc[4][4][4];
#pragma unroll
    for (int mt = 0; mt < 4; mt++)
#pragma unroll
        for (int nt = 0; nt < 4; nt++)
#pragma unroll
            for (int k = 0; k < 4; k++) acc[mt][nt][k] = 0.f;

    gemm_mainloop(sb, p, tid, ID / KC, acc);

    int wid = tid >> 5, lane = tid & 31;
    int wm = (wid & 1) * 64, wn = (wid >> 1) * 32;
    int g = lane >> 2, t = lane & 3;
#pragma unroll
    for (int mt = 0; mt < 4; mt++) {
#pragma unroll
        for (int half = 0; half < 2; half++) {
            int r = wm + mt * 16 + g + half * 8;
            int gi = m0 + r;
            if (gi < cnt) {
                float* orow = g_fc + (size_t)(roff + gi) * 2048 + n0 + wn;
#pragma unroll
                for (int nt = 0; nt < 4; nt++) {
                    float2 v = half ? make_float2(acc[mt][nt][2], acc[mt][nt][3])
                                    : make_float2(acc[mt][nt][0], acc[mt][nt][1]);
                    *(float2*)(orow + nt * 8 + t * 2) = v;
                }
            }
        }
    }
}

// ---------------- kernel 6: combine ----------------
__global__ void combine_kernel(float* __restrict__ out_y, int T) {
    int idx = blockIdx.x * blockDim.x + threadIdx.x;
    int t = idx >> 9;
    if (t >= T) return;
    int c = (idx & 511) * 4;
    int4 s = g_slot[t];
    int r0 = g_off[s.x] + s.y;
    int r1 = g_off[s.z] + s.w;
    float w0 = g_wt[s.x][s.y];
    float w1 = g_wt[s.z][s.w];
    float4 p0 = *(const float4*)(g_fc + (size_t)r0 * 2048 + c);
    float4 p1 = *(const float4*)(g_fc + (size_t)r1 * 2048 + c);
    float4 v;
    v.x = w0 * p0.x + w1 * p1.x;
    v.y = w0 * p0.y + w1 * p1.y;
    v.z = w0 * p0.z + w1 * p1.z;
    v.w = w0 * p0.w + w1 * p1.w;
    *(float4*)(out_y + (size_t)t * HD + c) = v;
}

// ---------------- launch ----------------
extern "C" void kernel_launch(void* const* d_in, const int* in_sizes, int n_in,
                              void* d_out, int out_size) {
    const float* x   = (const float*)d_in[0];
    const float* wg  = (const float*)d_in[1];
    const float* wfc = (const float*)d_in[2];
    const float* wp  = (const float*)d_in[3];
    float* out = (float*)d_out;

    int T = in_sizes[0] / HD;
    if (T > TMAX) T = TMAX;

    float* out_y = out;
    long long need = (long long)T * HD + (long long)T * NE;
    float* out_logits = ((long long)out_size >= need) ? out + (size_t)T * HD : nullptr;

    cudaFuncSetAttribute(fc_mma_kernel,   cudaFuncAttributeMaxDynamicSharedMemorySize, DSMEM);
    cudaFuncSetAttribute(proj_mma_kernel, cudaFuncAttributeMaxDynamicSharedMemorySize, DSMEM);

    size_t nprep = X4 + WFC4 + WP4;
    prep_kernel<<<(unsigned)((nprep + 255) / 256), 256>>>(x, wfc, wp);
    router_kernel<<<(T * 32 + 255) / 256, 256>>>(x, wg, out_logits, T);
    offsets_kernel<<<1, 32>>>();

    dim3 g1(2 * ID / B_ROWS, TMAX / A_ROWS, NE);   // (16, 64, 8)
    fc_mma_kernel<<<g1, 256, DSMEM>>>();

    glu_kernel<<<RMAX, 256>>>();

    dim3 g2(HD / B_ROWS, TMAX / A_ROWS, NE);       // (16, 64, 8)
    proj_mma_kernel<<<g2, 256, DSMEM>>>();

    int ncmb = T * (HD / 4);
    combine_kernel<<<(ncmb + 255) / 256, 256>>>(out_y, T);
}